// round 17
// baseline (speedup 1.0000x reference)
#include <cuda_runtime.h>
#include <cstdint>

#define DINL __device__ __forceinline__

namespace {
constexpr int Bq = 4096, Dn = 1024, H1n = 2048, H2n = 1024, Cn = 64, NSTEPS = 20;
constexpr float BETA = 0.9f, THR = 1.0f;
constexpr int I8_A = 128 * 128, I8_B = 128 * 128;
constexpr int I8_STAGE = I8_A + I8_B;               // 32 KB
constexpr int SMEM_I8 = 3 * I8_STAGE + 1024;        // ~97 KB -> 2 CTAs/SM
constexpr int NL1 = 512;                            // L1 tiles per step (16 x 32)
}

__device__ float g_mem1[(size_t)Bq * H1n];
__device__ float g_mem2[(size_t)Bq * H2n];
__device__ float g_spk [(size_t)Bq * H2n];
__device__ int8_t g_s1b[(size_t)Bq * H1n];
__device__ int8_t g_s2b[(size_t)Bq * H2n];
__device__ int g_cnt[32];
// int8 3-window x splits (t0 only)
__device__ int8_t g_xj0[(size_t)Bq * Dn];
__device__ int8_t g_xj1[(size_t)Bq * Dn];
__device__ int8_t g_xj2[(size_t)Bq * Dn];
// int8 3-window weight splits
__device__ int8_t g_w1i0[(size_t)H1n * Dn];
__device__ int8_t g_w1i1[(size_t)H1n * Dn];
__device__ int8_t g_w1i2[(size_t)H1n * Dn];
__device__ int8_t g_w2i0[(size_t)H2n * H1n];
__device__ int8_t g_w2i1[(size_t)H2n * H1n];
__device__ int8_t g_w2i2[(size_t)H2n * H1n];

DINL uint32_t smem_u32(const void* p) {
    uint32_t a;
    asm("{ .reg .u64 t; cvta.to.shared.u64 t, %1; cvt.u32.u64 %0, t; }" : "=r"(a) : "l"(p));
    return a;
}
DINL void cp16(uint32_t dst, const void* src) {
    asm volatile("cp.async.cg.shared.global [%0], [%1], 16;" :: "r"(dst), "l"(src));
}
DINL void cp_commit() { asm volatile("cp.async.commit_group;" ::: "memory"); }
DINL void cp_wait1()  { asm volatile("cp.async.wait_group 1;" ::: "memory"); }
DINL void cp_wait0()  { asm volatile("cp.async.wait_group 0;" ::: "memory"); }
DINL void ldsm4(uint32_t& r0, uint32_t& r1, uint32_t& r2, uint32_t& r3, uint32_t addr) {
    asm volatile("ldmatrix.sync.aligned.m8n8.x4.shared.b16 {%0,%1,%2,%3}, [%4];"
                 : "=r"(r0), "=r"(r1), "=r"(r2), "=r"(r3) : "r"(addr));
}
DINL void mma16832s8(int* c, const uint32_t* a, const uint32_t* b) {
    asm volatile(
        "mma.sync.aligned.m16n8k32.row.col.s32.s8.s8.s32 "
        "{%0,%1,%2,%3},{%4,%5,%6,%7},{%8,%9},{%0,%1,%2,%3};"
        : "+r"(c[0]), "+r"(c[1]), "+r"(c[2]), "+r"(c[3])
        : "r"(a[0]), "r"(a[1]), "r"(a[2]), "r"(a[3]), "r"(b[0]), "r"(b[1]));
}
DINL int ld_acquire(const int* p) {
    int v;
    asm volatile("ld.acquire.gpu.global.s32 %0, [%1];" : "=r"(v) : "l"(p));
    return v;
}

__global__ void zero_kernel() {
    size_t i = (size_t)blockIdx.x * blockDim.x + threadIdx.x;
    size_t stride = (size_t)gridDim.x * blockDim.x;
    const float4 z = make_float4(0.f, 0.f, 0.f, 0.f);
    for (size_t j = i; j < (size_t)Bq * H1n / 4; j += stride)
        reinterpret_cast<float4*>(g_mem1)[j] = z;
    for (size_t j = i; j < (size_t)Bq * H2n / 4; j += stride) {
        reinterpret_cast<float4*>(g_mem2)[j] = z;
        reinterpret_cast<float4*>(g_spk )[j] = z;
    }
    if (i < 32) g_cnt[i] = 0;
}

// 3-window int8 split for weights: w = i0*2^-9 + i1*2^-16 + i2*2^-23
__global__ void split_w(const float* __restrict__ src, size_t n, int which) {
    int8_t *p0, *p1, *p2;
    if (which == 0) { p0 = g_w1i0; p1 = g_w1i1; p2 = g_w1i2; }
    else            { p0 = g_w2i0; p1 = g_w2i1; p2 = g_w2i2; }
    size_t i = (size_t)blockIdx.x * blockDim.x + threadIdx.x;
    size_t stride = (size_t)gridDim.x * blockDim.x;
    for (size_t j = i; j < n; j += stride) {
        float v = src[j];
        float t0 = fminf(fmaxf(rintf(v * 0x1p9f), -127.f), 127.f);
        float r  = v - t0 * 0x1p-9f;
        float t1 = fminf(fmaxf(rintf(r * 0x1p16f), -127.f), 127.f);
        r -= t1 * 0x1p-16f;
        float t2 = fminf(fmaxf(rintf(r * 0x1p23f), -127.f), 127.f);
        p0[j] = (int8_t)(int)t0;
        p1[j] = (int8_t)(int)t1;
        p2[j] = (int8_t)(int)t2;
    }
}

// 3-window int8 split for x: x = j0*2^-4 + j1*2^-11 + j2*2^-18
__global__ void split_x(const float* __restrict__ src, size_t n) {
    size_t i = (size_t)blockIdx.x * blockDim.x + threadIdx.x;
    size_t stride = (size_t)gridDim.x * blockDim.x;
    for (size_t j = i; j < n; j += stride) {
        float v = src[j];
        float t0 = fminf(fmaxf(rintf(v * 0x1p4f), -127.f), 127.f);
        float r  = v - t0 * 0x1p-4f;
        float t1 = fminf(fmaxf(rintf(r * 0x1p11f), -127.f), 127.f);
        r -= t1 * 0x1p-11f;
        float t2 = fminf(fmaxf(rintf(r * 0x1p18f), -127.f), 127.f);
        g_xj0[j] = (int8_t)(int)t0;
        g_xj1[j] = (int8_t)(int)t1;
        g_xj2[j] = (int8_t)(int)t2;
    }
}

// ---------- one 128x128 int8 GEMM tile + fused LIF ----------
// LAYER 0: t0 layer-1 (x windows, 6 passes); LAYER 1: layer-1; LAYER 2: layer-2.
template<int LAYER>
DINL void tile_gemm(char* smraw, int bx, int by, const float* __restrict__ bias, int t) {
    constexpr int KDIM = (LAYER == 2) ? H1n : ((LAYER == 1) ? H2n : Dn);
    constexpr int NDIM = (LAYER == 2) ? H2n : H1n;
    constexpr bool SPK = (LAYER == 2);
    constexpr int KC = KDIM / 128;
    constexpr int NPASS = (LAYER == 0) ? 6 : 3;
    constexpr int NC = NPASS * KC;
    constexpr int CB1 = 1 * KC - 1;
    constexpr int CB2 = (LAYER == 0) ? (3 * KC - 1) : (2 * KC - 1);

    const uint32_t smbase = smem_u32(smraw);
    const uint32_t tb = (smbase + 1023u) & ~1023u;

    const int tid  = threadIdx.x;
    const int wid  = tid >> 5;
    const int lane = tid & 31;
    const int wm = wid >> 2;
    const int wn = wid & 3;
    const int m0  = by * 128;
    const int n0c = bx * 128;

    // L2 waits until all 16 L1 tiles of its m-block have signalled this step.
    if (LAYER == 2) {
        const int target = 16 * (t + 1);
        while (ld_acquire(&g_cnt[by]) < target) __nanosleep(64);
    }

    const int8_t* Ap[NPASS];
    const int8_t* Bp[NPASS];
    if (LAYER == 0) {
        Ap[0] = g_xj0; Bp[0] = g_w1i0;
        Ap[1] = g_xj0; Bp[1] = g_w1i1;
        Ap[2] = g_xj1; Bp[2] = g_w1i0;
        Ap[3] = g_xj0; Bp[3] = g_w1i2;
        Ap[4] = g_xj1; Bp[4] = g_w1i1;
        Ap[5] = g_xj2; Bp[5] = g_w1i0;
    } else if (LAYER == 1) {
        Ap[0] = g_s2b; Bp[0] = g_w1i0;
        Ap[1] = g_s2b; Bp[1] = g_w1i1;
        Ap[2] = g_s2b; Bp[2] = g_w1i2;
    } else {
        Ap[0] = g_s1b; Bp[0] = g_w2i0;
        Ap[1] = g_s1b; Bp[1] = g_w2i1;
        Ap[2] = g_s1b; Bp[2] = g_w2i2;
    }

    float* mem = (LAYER == 2) ? g_mem2 : g_mem1;
    int8_t* sout = (LAYER == 2) ? g_s2b : g_s1b;

    const int lrow = tid >> 3;
    const int lc16 = tid & 7;
    auto load_chunk = [&](int j) {
        const int p  = j / KC;
        const int kc = j - p * KC;
        const uint32_t sa = tb + (uint32_t)(j % 3) * I8_STAGE;
        const uint32_t sb = sa + I8_A;
        const int8_t* As = Ap[p] + (size_t)m0 * KDIM + kc * 128 + lc16 * 16;
        const int8_t* Bs = Bp[p] + (size_t)n0c * KDIM + kc * 128 + lc16 * 16;
        #pragma unroll
        for (int q = 0; q < 4; q++) {
            int row = lrow + q * 32;
            uint32_t off = (uint32_t)row * 128 + (uint32_t)((lc16 ^ (row & 7)) << 4);
            cp16(sa + off, As + (size_t)row * KDIM);
            cp16(sb + off, Bs + (size_t)row * KDIM);
        }
        cp_commit();
    };

    const int aRow  = wm * 64 + (lane & 15);
    const uint32_t aXor = (uint32_t)(aRow & 7);
    uint32_t aob[4];
    #pragma unroll
    for (int f = 0; f < 4; f++) aob[f] = (uint32_t)(aRow + f * 16) * 128;
    const uint32_t aC16 = (uint32_t)(lane >> 4);
    const int bg     = lane >> 3;
    const int btile  = bg >> 1;
    const int bkhalf = bg & 1;
    const int bN     = wn * 32 + btile * 8 + (lane & 7);
    const uint32_t bXor = (uint32_t)(bN & 7);
    uint32_t bob[2];
    #pragma unroll
    for (int n2 = 0; n2 < 2; n2++) bob[n2] = (uint32_t)(bN + n2 * 16) * 128;

    int acc[4][4][4];
    #pragma unroll
    for (int f = 0; f < 4; f++)
        #pragma unroll
        for (int o = 0; o < 4; o++)
            #pragma unroll
            for (int q = 0; q < 4; q++) acc[f][o][q] = 0;

    load_chunk(0); load_chunk(1);

    for (int i = 0; i < NC; i++) {
        const int j = i + 2;
        if (j < NC) cp_wait1(); else cp_wait0();
        __syncthreads();
        if (j < NC) load_chunk(j);

        const uint32_t sa = tb + (uint32_t)(i % 3) * I8_STAGE;
        const uint32_t sb = sa + I8_A;
        #pragma unroll
        for (int ks = 0; ks < 4; ks++) {
            uint32_t af[4][4];
            #pragma unroll
            for (int f = 0; f < 4; f++) {
                uint32_t c16 = (uint32_t)(ks * 2) + aC16;
                ldsm4(af[f][0], af[f][1], af[f][2], af[f][3],
                      sa + aob[f] + ((c16 ^ aXor) << 4));
            }
            uint32_t bf[2][4];
            #pragma unroll
            for (int n2 = 0; n2 < 2; n2++) {
                uint32_t c16 = (uint32_t)(ks * 2 + bkhalf);
                ldsm4(bf[n2][0], bf[n2][1], bf[n2][2], bf[n2][3],
                      sb + bob[n2] + ((c16 ^ bXor) << 4));
            }
            #pragma unroll
            for (int f = 0; f < 4; f++)
                #pragma unroll
                for (int o = 0; o < 4; o++)
                    mma16832s8(acc[f][o], af[f], &bf[o >> 1][(o & 1) * 2]);
        }

        if (i == CB1 || i == CB2) {
            #pragma unroll
            for (int f = 0; f < 4; f++)
                #pragma unroll
                for (int o = 0; o < 4; o++)
                    #pragma unroll
                    for (int q = 0; q < 4; q++) acc[f][o][q] *= 128;
        }
    }

    const float S2 = (LAYER == 0) ? 0x1p-13f : 0x1p-9f;
    const float S1 = (LAYER == 0) ? 0x1p-20f : 0x1p-16f;
    const float S0 = (LAYER == 0) ? 0x1p-27f : 0x1p-23f;
    const int r4  = lane >> 2;
    const int cp2 = (lane & 3) * 2;
    const int ncolw = n0c + wn * 32;
    #pragma unroll
    for (int f = 0; f < 4; f++) {
        #pragma unroll
        for (int h = 0; h < 2; h++) {
            const int m = m0 + wm * 64 + f * 16 + h * 8 + r4;
            float* memrow = mem + (size_t)m * NDIM + ncolw;
            int8_t* srow = sout + (size_t)m * NDIM + ncolw;
            float* spkrow = g_spk + (size_t)m * NDIM + ncolw;
            #pragma unroll
            for (int o = 0; o < 4; o++) {
                const int nn = o * 8 + cp2;
                float hv[2];
                #pragma unroll
                for (int q = 0; q < 2; q++) {
                    int v  = acc[f][o][2 * h + q];
                    int q2 = v >> 14;
                    int r  = v - (q2 << 14);
                    int q1 = r >> 7;
                    int q0 = r - (q1 << 7);
                    hv[q] = bias[ncolw + nn + q]
                          + (float)q2 * S2 + (float)q1 * S1 + (float)q0 * S0;
                }
                float2 mv = *reinterpret_cast<float2*>(memrow + nn);
                float n0v = BETA * mv.x + hv[0] - ((mv.x > THR) ? THR : 0.f);
                float n1v = BETA * mv.y + hv[1] - ((mv.y > THR) ? THR : 0.f);
                *reinterpret_cast<float2*>(memrow + nn) = make_float2(n0v, n1v);
                char2 sp;
                sp.x = (n0v > THR) ? 1 : 0;
                sp.y = (n1v > THR) ? 1 : 0;
                *reinterpret_cast<char2*>(srow + nn) = sp;
                if (SPK) {
                    float2 pk = *reinterpret_cast<float2*>(spkrow + nn);
                    pk.x += (n0v > THR) ? 1.f : 0.f;
                    pk.y += (n1v > THR) ? 1.f : 0.f;
                    *reinterpret_cast<float2*>(spkrow + nn) = pk;
                }
            }
        }
    }

    // L1 signals its m-block completion
    if (LAYER != 2) {
        __threadfence();
        __syncthreads();
        if (tid == 0) atomicAdd(&g_cnt[by], 1);
    }
}

// ---------- fused step kernel: bids [0,512) = L1 tiles, [512,768) = L2 ----------
template<int IS_T0>
__global__ __launch_bounds__(256, 2) void step_kernel(
    const float* __restrict__ b1, const float* __restrict__ b2, int t)
{
    extern __shared__ char smraw[];
    const int bid = blockIdx.x;
    if (bid < NL1) {
        if (IS_T0) tile_gemm<0>(smraw, bid & 15, bid >> 4, b1, t);
        else       tile_gemm<1>(smraw, bid & 15, bid >> 4, b1, t);
    } else {
        const int lb = bid - NL1;
        tile_gemm<2>(smraw, lb & 7, lb >> 3, b2, t);
    }
}

__global__ __launch_bounds__(256) void out_kernel(
    const float* __restrict__ Wo,
    const float* __restrict__ bo,
    float* __restrict__ out)
{
    __shared__ float wsh[64 * 129];
    const int tid = threadIdx.x;
    const int c  = tid & 63;
    const int rr = tid >> 6;

    float acc[4] = {0.f, 0.f, 0.f, 0.f};
    for (int k0 = 0; k0 < H2n; k0 += 128) {
        __syncthreads();
        #pragma unroll
        for (int it = 0; it < 8; it++) {
            int l  = tid + it * 256;
            int c2 = l >> 5;
            int kk = (l & 31) * 4;
            float4 w4 = *reinterpret_cast<const float4*>(&Wo[(size_t)c2 * H2n + k0 + kk]);
            wsh[c2 * 129 + kk + 0] = w4.x;
            wsh[c2 * 129 + kk + 1] = w4.y;
            wsh[c2 * 129 + kk + 2] = w4.z;
            wsh[c2 * 129 + kk + 3] = w4.w;
        }
        __syncthreads();
        #pragma unroll
        for (int p = 0; p < 4; p++) {
            const int b = blockIdx.x * 16 + p * 4 + rr;
            const float* sp = &g_spk[(size_t)b * H2n + k0];
            #pragma unroll
            for (int k = 0; k < 128; k += 4) {
                float4 s4 = *reinterpret_cast<const float4*>(sp + k);
                acc[p] = fmaf(s4.x, wsh[c * 129 + k + 0], acc[p]);
                acc[p] = fmaf(s4.y, wsh[c * 129 + k + 1], acc[p]);
                acc[p] = fmaf(s4.z, wsh[c * 129 + k + 2], acc[p]);
                acc[p] = fmaf(s4.w, wsh[c * 129 + k + 3], acc[p]);
            }
        }
    }
    #pragma unroll
    for (int p = 0; p < 4; p++) {
        const int b = blockIdx.x * 16 + p * 4 + rr;
        out[(size_t)b * Cn + c] = acc[p] * (1.0f / NSTEPS) + bo[c];
    }
}

extern "C" void kernel_launch(void* const* d_in, const int* in_sizes, int n_in,
                              void* d_out, int out_size)
{
    const float* x  = (const float*)d_in[0];
    const float* W1 = (const float*)d_in[1];
    const float* b1 = (const float*)d_in[2];
    const float* W2 = (const float*)d_in[3];
    const float* b2 = (const float*)d_in[4];
    const float* Wo = (const float*)d_in[5];
    const float* bo = (const float*)d_in[6];
    float* out = (float*)d_out;

    cudaFuncSetAttribute(step_kernel<0>, cudaFuncAttributeMaxDynamicSharedMemorySize, SMEM_I8);
    cudaFuncSetAttribute(step_kernel<1>, cudaFuncAttributeMaxDynamicSharedMemorySize, SMEM_I8);

    zero_kernel<<<512, 256>>>();
    split_w<<<512, 256>>>(W1, (size_t)H1n * Dn, 0);
    split_w<<<512, 256>>>(W2, (size_t)H2n * H1n, 1);
    split_x<<<512, 256>>>(x, (size_t)Bq * Dn);

    step_kernel<1><<<768, 256, SMEM_I8>>>(b1, b2, 0);
    for (int t = 1; t < NSTEPS; t++)
        step_kernel<0><<<768, 256, SMEM_I8>>>(b1, b2, t);

    out_kernel<<<Bq / 16, 256>>>(Wo, bo, out);
}